// round 6
// baseline (speedup 1.0000x reference)
#include <cuda_runtime.h>
#include <cstdint>

// Scratch: per-node best key = (ordered(t) << 32) | (pos + 1). 0 == empty.
__device__ unsigned long long g_best[1 << 20];

// Map float bits to an order-preserving unsigned int (for non-NaN floats).
__device__ __forceinline__ unsigned int order_f32(float f) {
    unsigned int b = __float_as_uint(f);
    return (b & 0x80000000u) ? ~b : (b | 0x80000000u);
}

// Scatter with inline index-dtype detection and check-then-atomic filtering.
// g_best values only ever increase, so a stale __ldcg read can only cause a
// redundant atomicMax, never a missed one -> always correct.
__global__ void scatter_kernel(const void* __restrict__ index_raw,
                               const float* __restrict__ t, int E, int N) {
    // per-block dtype vote: for int64 < 2^31 odd 32-bit words are zero;
    // for int32 data they're real indices. Reads only words < E: safe.
    const int* idx32 = (const int*)index_raw;
    int w = 2 * threadIdx.x + 1;
    int found = (w < E && idx32[w] != 0) ? 1 : 0;
    int is32 = __syncthreads_or(found);

    int stride4 = gridDim.x * blockDim.x * 4;
    for (int base = (blockIdx.x * blockDim.x + threadIdx.x) * 4; base < E;
         base += stride4) {
        int cnt = min(4, E - base);
        if (is32 && cnt == 4) {
            int4 idx = *(const int4*)(idx32 + base);
            float4 tv = *(const float4*)(t + base);
            int ix[4] = {idx.x, idx.y, idx.z, idx.w};
            float tt[4] = {tv.x, tv.y, tv.z, tv.w};
            unsigned long long cur[4], key[4];
            bool ok[4];
#pragma unroll
            for (int k = 0; k < 4; k++) {
                ok[k] = (ix[k] >= 0 && ix[k] < N);
                key[k] = ((unsigned long long)order_f32(tt[k]) << 32) |
                         (unsigned int)(base + k + 1);
                cur[k] = ok[k] ? __ldcg(&g_best[ix[k]]) : ~0ull;
            }
#pragma unroll
            for (int k = 0; k < 4; k++) {
                if (ok[k] && key[k] > cur[k]) atomicMax(&g_best[ix[k]], key[k]);
            }
        } else {
            for (int k = 0; k < cnt; k++) {
                int e = base + k;
                long long idx = is32 ? (long long)idx32[e]
                                     : ((const long long*)index_raw)[e];
                if (idx < 0 || idx >= N) continue;
                unsigned long long key =
                    ((unsigned long long)order_f32(t[e]) << 32) |
                    (unsigned int)(e + 1);
                if (key > __ldcg(&g_best[(int)idx]))
                    atomicMax(&g_best[(int)idx], key);
            }
        }
    }
}

// Persistent gather for D==128: each warp handles groups of 8 nodes via
// grid-stride; 8 independent LDG.128 per thread (MLP=8), streaming stores so
// the output doesn't evict the gathered read-set from L2 across replays.
__global__ void gather_kernel_d128(const float4* __restrict__ msg,
                                   float4* __restrict__ out, int N, int E) {
    int lane = threadIdx.x & 31;
    int warp = (blockIdx.x * blockDim.x + threadIdx.x) >> 5;
    int warps_total = (gridDim.x * blockDim.x) >> 5;
    int ngroups = (N + 7) >> 3;

    for (int g = warp; g < ngroups; g += warps_total) {
        int n0 = g * 8;
        unsigned long long mykey = 0ull;
        if (lane < 8 && (n0 + lane) < N) mykey = g_best[n0 + lane];

        float4 v[8];
#pragma unroll
        for (int k = 0; k < 8; k++) {
            unsigned long long key = __shfl_sync(0xffffffffu, mykey, k);
            long long e = (long long)((unsigned int)key) - 1;
            v[k] = make_float4(0.f, 0.f, 0.f, 0.f);
            if (key != 0ull && e < (long long)E && (n0 + k) < N)
                v[k] = __ldg(&msg[(size_t)e * 32 + lane]);
        }
#pragma unroll
        for (int k = 0; k < 8; k++) {
            if ((n0 + k) < N) __stcs(&out[(size_t)(n0 + k) * 32 + lane], v[k]);
        }
    }
}

// Generic fallback: one warp per node, scalar strided.
__global__ void gather_kernel_generic(const float* __restrict__ msg,
                                      float* __restrict__ out, int N, int D, int E) {
    int warp = (blockIdx.x * blockDim.x + threadIdx.x) >> 5;
    int lane = threadIdx.x & 31;
    if (warp >= N) return;
    unsigned long long key = g_best[warp];
    size_t obase = (size_t)warp * D;
    long long e = (long long)((unsigned int)key) - 1;
    if (key == 0ull || e >= (long long)E) {
        for (int j = lane; j < D; j += 32) out[obase + j] = 0.f;
    } else {
        size_t ibase = (size_t)e * (size_t)D;
        for (int j = lane; j < D; j += 32) out[obase + j] = msg[ibase + j];
    }
}

extern "C" void kernel_launch(void* const* d_in, const int* in_sizes, int n_in,
                              void* d_out, int out_size) {
    const float* msg   = (const float*)d_in[0];  // [E, D] float32
    const void*  index = d_in[1];                // [E] int32 or int64
    const float* t     = (const float*)d_in[2];  // [E] float32

    int E = in_sizes[2];
    int D = in_sizes[0] / E;
    int N = out_size / D;
    if (N > (1 << 20)) N = (1 << 20);  // scratch capacity guard

    // 1) zero per-node best keys (memset node; atomicMax re-derivation is
    //    idempotent but start clean every call anyway)
    void* best_ptr = nullptr;
    cudaGetSymbolAddress(&best_ptr, g_best);
    cudaMemsetAsync(best_ptr, 0, (size_t)N * sizeof(unsigned long long), 0);

    // 2) scatter: persistent grid, 4 events/thread/iter, filtered atomics
    {
        int threads = 256;
        int blocks = 152 * 4;  // GB300: 152 SMs
        int need = (E + threads * 4 - 1) / (threads * 4);
        if (blocks > need) blocks = need;
        scatter_kernel<<<blocks, threads>>>(index, t, E, N);
    }

    // 3) gather winning rows
    if (D == 128) {
        int threads = 256;     // 8 warps/block
        int blocks = 152 * 8;  // exact multiple of SM count: no ragged wave
        int need = ((N + 7) / 8 + (threads / 32) - 1) / (threads / 32);
        if (blocks > need) blocks = need;
        gather_kernel_d128<<<blocks, threads>>>((const float4*)msg,
                                                (float4*)d_out, N, E);
    } else {
        int threads = 256;
        int warps_per_block = threads / 32;
        int blocks = (N + warps_per_block - 1) / warps_per_block;
        gather_kernel_generic<<<blocks, threads>>>(msg, (float*)d_out, N, D, E);
    }
}